// round 12
// baseline (speedup 1.0000x reference)
#include <cuda_runtime.h>
#include <math.h>
#include <stdint.h>

#define Tn 64
#define Bn 32
#define Hn 1024
#define Sn 64
#define Gn 4096
#define NB 128
#define NT 512

// ---- smem layout (bytes) ----
// ws[p]: 32 cols x 264 floats (pad)   -> 33792 each
// xr[p]: 32 rows x 268 floats (pad)   -> 34304 each
// xp (transposed pairs) aliases RED
// red: 1024 outs x 17                 -> 69632
// sums: 1024 floats                   -> 4096
#define WS0   0
#define WS_SZ 33792
#define WS1   33792
#define XR0   67584
#define XR_SZ 34304
#define XR1   101888
#define REDO  136192
#define SUMSO 205824
#define SMEM_BYTES 209920

__device__ float g_pre[(size_t)Tn * Bn * Gn];
__device__ float g_h[2][2 * Bn * Hn];
__device__ float g_c[2 * Bn * Hn];
__device__ float g_gamma[Bn * Hn];
__device__ float g_opart[Bn * Hn];
__device__ float g_ctx[Bn * Hn];
__device__ unsigned g_ctr;          // cumulative arrival counter
__device__ volatile unsigned g_rel; // cumulative release phase

// ---------------- primitives ----------------
__device__ __forceinline__ void ffma2(unsigned long long& d, unsigned long long a,
                                      unsigned long long b) {
    asm volatile("fma.rn.f32x2 %0, %1, %2, %0;" : "+l"(d) : "l"(a), "l"(b));
}
__device__ __forceinline__ void cp16(uint32_t saddr, const void* g) {
    asm volatile("cp.async.cg.shared.global [%0], [%1], 16;" :: "r"(saddr), "l"(g));
}
#define CP_COMMIT() asm volatile("cp.async.commit_group;" ::: "memory")
#define CP_WAIT1()  asm volatile("cp.async.wait_group 1;" ::: "memory")
#define CP_WAIT0()  asm volatile("cp.async.wait_group 0;" ::: "memory")
__device__ __forceinline__ unsigned ld_acq(volatile unsigned* p) {
    unsigned v;
    asm volatile("ld.acquire.gpu.u32 %0, [%1];" : "=r"(v) : "l"((const unsigned*)p) : "memory");
    return v;
}
__device__ __forceinline__ void st_rel(volatile unsigned* p, unsigned v) {
    asm volatile("st.release.gpu.u32 [%0], %1;" :: "l"((unsigned*)p), "r"(v) : "memory");
}
__device__ __forceinline__ float lo32(unsigned long long v) { return __uint_as_float((unsigned)v); }
__device__ __forceinline__ float hi32(unsigned long long v) { return __uint_as_float((unsigned)(v >> 32)); }

// grid barrier: cumulative atomic counter, last arriver releases, tight spin.
__device__ void gsync(unsigned tgt) {
    __threadfence();
    __syncthreads();
    if (threadIdx.x == 0) {
        const unsigned old = atomicAdd(&g_ctr, 1u);
        if (old == tgt * NB - 1u) {
            st_rel(&g_rel, tgt);
        } else {
            while ((int)(ld_acq(&g_rel) - tgt) < 0) { }
        }
        __threadfence();  // invalidate stale L1 before reading peers' data
    }
    __syncthreads();
}

// ---------------- GEMM v2: warps = K-slices, lanes = batch, W broadcast ----------
struct TileArgs {
    const float *X1, *X2;   // X2 used for k>=1024
    const float *W1, *W2;   // W2 used for k>=1024
    int ldw;
    int col0;               // linear col map: col = col0 + c
    int interleave;         // 1: col = (c>>3)*Hn + jbase + (c&7)
    int jbase;
    const int* gather; int m0;
    int nch;                // K/256
};

template<int NCOL>
__device__ __forceinline__ void stage2(const TileArgs& a, int ch, char* smem, int p) {
    const int koff0 = ch * 256;
    const float* X = (koff0 >= 1024) ? a.X2 : a.X1;
    const float* W = (koff0 >= 1024) ? a.W2 : a.W1;
    const int koff = koff0 & 1023;
    const uint32_t base = (uint32_t)__cvta_generic_to_shared(smem);
    const uint32_t wsb = base + (p ? WS1 : WS0);
    const uint32_t xrb = base + (p ? XR1 : XR0);
    const int tid = threadIdx.x;
    // W: NCOL cols x 64 float4 each, row stride 66 float4 (264 floats)
    #pragma unroll
    for (int i = 0; i < NCOL / 8; i++) {
        const int e = tid + i * 512;
        const int c = e >> 6, k4 = e & 63;
        const int grow = a.interleave ? ((c >> 3) * Hn + a.jbase + (c & 7)) : (a.col0 + c);
        cp16(wsb + (uint32_t)(c * 66 + k4) * 16, W + (size_t)grow * a.ldw + koff + k4 * 4);
    }
    // X: 32 rows x 64 float4, row stride 67 float4 (268 floats)
    #pragma unroll
    for (int i = 0; i < 4; i++) {
        const int e = tid + i * 512;
        const int row = e >> 6, k4 = e & 63;
        const int grow = a.gather ? __ldg(a.gather + a.m0 + row) : row;
        cp16(xrb + (uint32_t)(row * 67 + k4) * 16, X + (size_t)grow * Hn + koff + k4 * 4);
    }
    CP_COMMIT();
}

// transpose xr[p] (32 x 268 floats) -> xp[k2][b] (128 x 32 ulonglong), conflict-free
__device__ __forceinline__ void xpose(char* smem, int p) {
    const float* xr = (const float*)(smem + (p ? XR1 : XR0));
    unsigned long long* xp = (unsigned long long*)(smem + REDO);
    const int b = threadIdx.x & 31, kseg = threadIdx.x >> 5;   // 16 segs x 16 k
    const float* src = xr + b * 268 + kseg * 16;
    #pragma unroll
    for (int j = 0; j < 4; j++) {
        const float4 v = *(const float4*)(src + j * 4);
        const int k2 = kseg * 8 + j * 2;
        unsigned long long w0 = ((unsigned long long)__float_as_uint(v.y) << 32) | __float_as_uint(v.x);
        unsigned long long w1 = ((unsigned long long)__float_as_uint(v.w) << 32) | __float_as_uint(v.z);
        xp[(size_t)k2 * 32 + b] = w0;
        xp[(size_t)(k2 + 1) * 32 + b] = w1;
    }
}

// Result: sums[c*32 + b] for c in [0, NCOL)
template<int NCOL>
__device__ void gemm2(const TileArgs& a, char* smem) {
    const int tid = threadIdx.x;
    const int lane = tid & 31;       // batch
    const int wq = tid >> 5;         // k-slice (16 warps x 16 k per chunk)
    unsigned long long acc[NCOL];
    #pragma unroll
    for (int c = 0; c < NCOL; c++) acc[c] = 0ull;

    stage2<NCOL>(a, 0, smem, 0);
    for (int ch = 0; ch < a.nch; ch++) {
        __syncthreads();   // protect buffer (ch&1) from overwrite vs prior compute
        if (ch + 1 < a.nch) stage2<NCOL>(a, ch + 1, smem, (ch + 1) & 1);
        if (ch + 1 < a.nch) { CP_WAIT1(); } else { CP_WAIT0(); }
        __syncthreads();   // chunk ch data visible to all
        xpose(smem, ch & 1);
        __syncthreads();   // xp ready
        // x pairs for this warp's k-slice (reused across all NCOL cols)
        const unsigned long long* xp = (const unsigned long long*)(smem + REDO);
        unsigned long long x2[8];
        #pragma unroll
        for (int kp = 0; kp < 8; kp++) x2[kp] = xp[(size_t)(wq * 8 + kp) * 32 + lane];
        const unsigned long long* wsu =
            (const unsigned long long*)(smem + ((ch & 1) ? WS1 : WS0));
        #pragma unroll
        for (int c = 0; c < NCOL; c++) {
            const ulonglong2* wrow = (const ulonglong2*)(wsu + c * 132 + wq * 8);
            #pragma unroll
            for (int q = 0; q < 4; q++) {
                const ulonglong2 wv = wrow[q];        // warp-uniform broadcast
                ffma2(acc[c], x2[q * 2], wv.x);
                ffma2(acc[c], x2[q * 2 + 1], wv.y);
            }
        }
    }
    __syncthreads();       // all compute done before red overwrites xp region
    float* red = (float*)(smem + REDO);
    #pragma unroll
    for (int c = 0; c < NCOL; c++)
        red[(c * 32 + lane) * 17 + wq] = lo32(acc[c]) + hi32(acc[c]);
    __syncthreads();
    float* sums = (float*)(smem + SUMSO);
    for (int o = tid; o < NCOL * 32; o += NT) {
        float s = 0.f;
        const float* rp = red + o * 17;
        #pragma unroll
        for (int w = 0; w < 16; w++) s += rp[w];
        sums[o] = s;
    }
    __syncthreads();
}

// ---------------- epilogues ----------------
__device__ __forceinline__ void lstm_epi(const float* sums, int tile, int t, int layer,
    const float* b_ih, const float* b_hh, float* hNew, float* cSt) {
    const int tid = threadIdx.x;
    if (tid < 256) {
        const int b = tid & 31, jj = tid >> 5;
        const int col = tile * 8 + jj;
        const float* bi = b_ih + layer * Gn;
        const float* bh = b_hh + layer * Gn;
        float gi = sums[(jj) * 32 + b]      + bi[col]          + bh[col];
        float gf = sums[(8 + jj) * 32 + b]  + bi[Hn + col]     + bh[Hn + col];
        float gg = sums[(16 + jj) * 32 + b] + bi[2 * Hn + col] + bh[2 * Hn + col];
        float go = sums[(24 + jj) * 32 + b] + bi[3 * Hn + col] + bh[3 * Hn + col];
        if (layer == 0) {
            const float* pr = g_pre + ((size_t)t * Bn + b) * Gn;
            gi += pr[col]; gf += pr[Hn + col]; gg += pr[2 * Hn + col]; go += pr[3 * Hn + col];
        }
        gi = 1.f / (1.f + expf(-gi));
        gf = 1.f / (1.f + expf(-gf));
        gg = tanhf(gg);
        go = 1.f / (1.f + expf(-go));
        float* c = cSt + layer * Bn * Hn;
        const float cn = gf * c[b * Hn + col] + gi * gg;
        c[b * Hn + col] = cn;
        (hNew + layer * Bn * Hn)[b * Hn + col] = go * tanhf(cn);
    }
    __syncthreads();
}

__device__ void attn(const float* __restrict__ contexts, char* smem) {
    const int b = blockIdx.x, tid = threadIdx.x;
    float* gam = (float*)smem;
    float* sc = gam + Hn;
    for (int j = tid; j < Hn; j += NT) gam[j] = g_gamma[b * Hn + j];
    __syncthreads();
    const int w = tid >> 5, lane = tid & 31;
    for (int s = w; s < Sn; s += 16) {
        const float* cr = contexts + ((size_t)b * Sn + s) * Hn;
        float p = 0.f;
        for (int j = lane; j < Hn; j += 32) p += cr[j] * gam[j];
        #pragma unroll
        for (int o = 16; o; o >>= 1) p += __shfl_down_sync(0xffffffffu, p, o);
        if (!lane) sc[s] = p;
    }
    __syncthreads();
    if (tid == 0) {
        float m = -1e30f;
        for (int i = 0; i < Sn; i++) m = fmaxf(m, sc[i]);
        float su = 0.f;
        for (int i = 0; i < Sn; i++) { float e = expf(sc[i] - m); sc[i] = e; su += e; }
        const float inv = 1.f / su;
        for (int i = 0; i < Sn; i++) sc[i] *= inv;
    }
    __syncthreads();
    for (int j = tid; j < Hn; j += NT) {
        float a2 = 0.f;
        #pragma unroll 8
        for (int s = 0; s < Sn; s++) a2 += sc[s] * contexts[((size_t)b * Sn + s) * Hn + j];
        g_ctx[b * Hn + j] = a2;
    }
    __syncthreads();
}

// ---------------- persistent kernel ----------------
__global__ void __launch_bounds__(NT, 1) decoder(
    const int* __restrict__ tokens, const float* __restrict__ contexts,
    const float* __restrict__ emb,
    const float* __restrict__ W_ih, const float* __restrict__ W_hh,
    const float* __restrict__ b_ih, const float* __restrict__ b_hh,
    const float* __restrict__ W_in, const float* __restrict__ b_in,
    const float* __restrict__ W_out, const float* __restrict__ b_out,
    const float* __restrict__ h0, const float* __restrict__ c0,
    float* __restrict__ out)
{
    extern __shared__ char smem[];
    const unsigned base = g_rel;
    unsigned ph = 0;
    const int tid = threadIdx.x;
    float* sums = (float*)(smem + SUMSO);

    // state init
    for (int i = blockIdx.x * NT + tid; i < 2 * Bn * Hn; i += NB * NT) {
        g_h[0][i] = h0[i];
        g_c[i] = c0[i];
    }

    // pre-phase: g_pre[t*B+b][gatecol] = emb[tokens] @ W_ih0^T
    for (int tt = blockIdx.x; tt < 64 * 128; tt += NB) {
        const int ctile = tt & 127;
        TileArgs a;
        a.X1 = emb; a.X2 = emb; a.W1 = W_ih; a.W2 = W_ih; a.ldw = Hn;
        a.interleave = 1; a.jbase = ctile * 8; a.col0 = 0;
        a.gather = tokens; a.m0 = (tt >> 7) * 32; a.nch = 4;
        gemm2<32>(a, smem);
        #pragma unroll
        for (int r = 0; r < 2; r++) {
            const int o = tid + r * 512;
            const int c = o >> 5, b = o & 31;
            const int col = (c >> 3) * Hn + ctile * 8 + (c & 7);
            g_pre[(size_t)(a.m0 + b) * Gn + col] = sums[o];
        }
        __syncthreads();
    }
    gsync(base + ++ph);

    for (int t = 0; t < Tn; t++) {
        const int p = t & 1;
        float* hOld = g_h[p];
        float* hNew = g_h[p ^ 1];

        // A: layer-0 gates = pre[t] + h0_old @ W_hh0^T
        {
            TileArgs a;
            a.X1 = hOld; a.X2 = hOld; a.W1 = W_hh; a.W2 = W_hh; a.ldw = Hn;
            a.interleave = 1; a.jbase = blockIdx.x * 8; a.col0 = 0;
            a.gather = nullptr; a.m0 = 0; a.nch = 4;
            gemm2<32>(a, smem);
            lstm_epi(sums, blockIdx.x, t, 0, b_ih, b_hh, hNew, g_c);
        }
        gsync(base + ++ph);

        // B: layer-1 gates = h0_new @ W_ih1^T + h1_old @ W_hh1^T (K=2048)
        {
            TileArgs a;
            a.X1 = hNew; a.X2 = hOld + Bn * Hn;
            a.W1 = W_ih + (size_t)Gn * Hn; a.W2 = W_hh + (size_t)Gn * Hn; a.ldw = Hn;
            a.interleave = 1; a.jbase = blockIdx.x * 8; a.col0 = 0;
            a.gather = nullptr; a.m0 = 0; a.nch = 8;
            gemm2<32>(a, smem);
            lstm_epi(sums, blockIdx.x, t, 1, b_ih, b_hh, hNew, g_c);
        }
        gsync(base + ++ph);

        // C: gamma = h1 @ W_in^T + b_in  (128 blocks x 8 cols)
        {
            TileArgs a;
            a.X1 = hNew + Bn * Hn; a.X2 = a.X1;
            a.W1 = W_in; a.W2 = W_in; a.ldw = Hn;
            a.interleave = 0; a.jbase = 0; a.col0 = blockIdx.x * 8;
            a.gather = nullptr; a.m0 = 0; a.nch = 4;
            gemm2<8>(a, smem);
            if (tid < 256) {
                const int c = tid >> 5, b = tid & 31;
                const int col = a.col0 + c;
                g_gamma[b * Hn + col] = sums[tid] + b_in[col];
            }
            __syncthreads();
        }
        gsync(base + ++ph);

        // D: attention (blocks 0..31) || opart = h1 @ W_out[:,H:]^T (blocks 32..95)
        if (blockIdx.x < 32) {
            attn(contexts, smem);
        } else if (blockIdx.x < 96) {
            TileArgs a;
            a.X1 = hNew + Bn * Hn; a.X2 = a.X1;
            a.W1 = W_out + Hn; a.W2 = a.W1; a.ldw = 2 * Hn;
            a.interleave = 0; a.jbase = 0; a.col0 = (blockIdx.x - 32) * 16;
            a.gather = nullptr; a.m0 = 0; a.nch = 4;
            gemm2<16>(a, smem);
            {
                const int c = tid >> 5, b = tid & 31;
                const int col = a.col0 + c;
                g_opart[b * Hn + col] = sums[tid];
            }
            __syncthreads();
        }
        gsync(base + ++ph);

        // E: out[t] = tanh(ctx @ W_out[:, :H]^T + opart + b_out)
        {
            TileArgs a;
            a.X1 = g_ctx; a.X2 = g_ctx; a.W1 = W_out; a.W2 = W_out; a.ldw = 2 * Hn;
            a.interleave = 0; a.jbase = 0; a.col0 = blockIdx.x * 8;
            a.gather = nullptr; a.m0 = 0; a.nch = 4;
            gemm2<8>(a, smem);
            if (tid < 256) {
                const int c = tid >> 5, b = tid & 31;
                const int col = a.col0 + c;
                out[(size_t)t * Bn * Hn + b * Hn + col] =
                    tanhf(sums[tid] + g_opart[b * Hn + col] + b_out[col]);
            }
            __syncthreads();
        }
        // next A's gsync covers E
    }
    gsync(base + ++ph);

    // emit hT (in g_h[0] after even Tn) and cT
    for (int i = blockIdx.x * NT + tid; i < 2 * Bn * Hn; i += NB * NT) {
        out[(size_t)Tn * Bn * Hn + i] = g_h[0][i];
        out[(size_t)Tn * Bn * Hn + 2 * Bn * Hn + i] = g_c[i];
    }
}

// ---------------- launch ----------------
extern "C" void kernel_launch(void* const* d_in, const int* in_sizes, int n_in,
                              void* d_out, int out_size)
{
    const int*   tokens   = (const int*)  d_in[0];
    const float* h0       = (const float*)d_in[1];
    const float* c0       = (const float*)d_in[2];
    const float* contexts = (const float*)d_in[3];
    const float* emb      = (const float*)d_in[4];
    const float* W_ih     = (const float*)d_in[5];
    const float* W_hh     = (const float*)d_in[6];
    const float* b_ih     = (const float*)d_in[7];
    const float* b_hh     = (const float*)d_in[8];
    const float* W_in     = (const float*)d_in[9];
    const float* b_in     = (const float*)d_in[10];
    const float* W_out    = (const float*)d_in[11];
    const float* b_out    = (const float*)d_in[12];
    float* out = (float*)d_out;

    static bool configured = false;
    if (!configured) {
        cudaFuncSetAttribute(decoder, cudaFuncAttributeMaxDynamicSharedMemorySize, SMEM_BYTES);
        configured = true;
    }
    decoder<<<NB, NT, SMEM_BYTES>>>(tokens, contexts, emb, W_ih, W_hh, b_ih, b_hh,
                                    W_in, b_in, W_out, b_out, h0, c0, out);
}

// round 16
// speedup vs baseline: 1.1189x; 1.1189x over previous
#include <cuda_runtime.h>
#include <math.h>
#include <stdint.h>

#define Tn 64
#define Bn 32
#define Hn 1024
#define Sn 64
#define Gn 4096
#define NB 128
#define NT 512

// ---- smem layout (bytes) ----
// tiles: 32 rows x 260 floats (stride 260 => bank offset 4/row, conflict-free)
#define TILE_B (32 * 260 * 4)      // 33280
#define XS0   0
#define WS0   33280
#define XS1   66560
#define WS1   99840
#define REDO  133120               // 8192 floats = 32768 B
#define SUMSO 165888               // 1024 floats = 4096 B
#define MBARO 169984               // 2 mbarriers (16 B)
#define SMEM_BYTES 170240

__device__ float g_pre[(size_t)Tn * Bn * Gn];
__device__ float g_h[2][2 * Bn * Hn];
__device__ float g_c[2 * Bn * Hn];
__device__ float g_gamma[Bn * Hn];
__device__ float g_opart[Bn * Hn];
__device__ float g_ctx[Bn * Hn];
__device__ unsigned g_ctr;          // cumulative arrival counter
__device__ volatile unsigned g_rel; // cumulative release phase

// ---------------- primitives ----------------
__device__ __forceinline__ void ffma2(unsigned long long& d, unsigned long long a,
                                      unsigned long long b) {
    asm volatile("fma.rn.f32x2 %0, %1, %2, %0;" : "+l"(d) : "l"(a), "l"(b));
}
__device__ __forceinline__ void bulkcp(uint32_t dst, const void* src, uint32_t bytes,
                                       uint32_t mbar) {
    asm volatile(
        "cp.async.bulk.shared::cta.global.mbarrier::complete_tx::bytes [%0], [%1], %2, [%3];"
        :: "r"(dst), "l"(src), "r"(bytes), "r"(mbar) : "memory");
}
__device__ __forceinline__ void mbar_init(uint32_t mbar, unsigned cnt) {
    asm volatile("mbarrier.init.shared.b64 [%0], %1;" :: "r"(mbar), "r"(cnt) : "memory");
}
__device__ __forceinline__ void mbar_expect_tx(uint32_t mbar, unsigned bytes) {
    asm volatile("mbarrier.arrive.expect_tx.shared.b64 _, [%0], %1;"
                 :: "r"(mbar), "r"(bytes) : "memory");
}
__device__ __forceinline__ void mbar_wait(uint32_t mbar, unsigned parity) {
    unsigned done;
    asm volatile(
        "{\n\t.reg .pred p;\n\t"
        "mbarrier.try_wait.parity.acquire.cta.shared::cta.b64 p, [%1], %2;\n\t"
        "selp.b32 %0, 1, 0, p;\n\t}"
        : "=r"(done) : "r"(mbar), "r"(parity) : "memory");
    if (!done) {
        asm volatile(
            "{\n\t.reg .pred P1;\n\t"
            "WAIT_LOOP_%=:\n\t"
            "mbarrier.try_wait.parity.acquire.cta.shared::cta.b64 P1, [%0], %1, 0x989680;\n\t"
            "@P1 bra.uni WAIT_DONE_%=;\n\t"
            "bra.uni WAIT_LOOP_%=;\n\t"
            "WAIT_DONE_%=:\n\t}"
            :: "r"(mbar), "r"(parity) : "memory");
    }
}
__device__ __forceinline__ unsigned ld_acq(volatile unsigned* p) {
    unsigned v;
    asm volatile("ld.acquire.gpu.u32 %0, [%1];" : "=r"(v) : "l"((const unsigned*)p) : "memory");
    return v;
}
__device__ __forceinline__ void st_rel(volatile unsigned* p, unsigned v) {
    asm volatile("st.release.gpu.u32 [%0], %1;" :: "l"((unsigned*)p), "r"(v) : "memory");
}
__device__ __forceinline__ float lo32(unsigned long long v) { return __uint_as_float((unsigned)v); }
__device__ __forceinline__ float hi32(unsigned long long v) { return __uint_as_float((unsigned)(v >> 32)); }

// grid barrier: cumulative atomic counter, last arriver releases, tight spin.
__device__ void gsync(unsigned tgt) {
    __threadfence();
    __syncthreads();
    if (threadIdx.x == 0) {
        const unsigned old = atomicAdd(&g_ctr, 1u);
        if (old == tgt * NB - 1u) {
            st_rel(&g_rel, tgt);
        } else {
            while ((int)(ld_acq(&g_rel) - tgt) < 0) { }
        }
        __threadfence();  // invalidate stale L1 before reading peers' data
    }
    __syncthreads();
}

// ---------------- GEMM v3: v1 compute layout + bulk-copy staging ----------------
struct TileArgs {
    const float *X1, *X2;   // X2 used for k>=1024
    const float *W1, *W2;   // W2 used for k>=1024
    int ldw;
    int col0;               // linear col map: col = col0 + c
    int interleave;         // 1: col = (c>>3)*Hn + jbase + (c&7)
    int jbase;
    const int* gather; int m0;
    int nch;                // K/256
};

// stage chunk ch into buffer p: warp 0 issues 32 X-row + NCOL W-row bulk copies
template<int NCOL>
__device__ __forceinline__ void stage3(const TileArgs& a, int ch, char* smem, int p,
                                       uint32_t mbar) {
    const int tid = threadIdx.x;
    if (tid >= 32) return;
    const int koff0 = ch * 256;
    const float* X = (koff0 >= 1024) ? a.X2 : a.X1;
    const float* W = (koff0 >= 1024) ? a.W2 : a.W1;
    const int koff = koff0 & 1023;
    const uint32_t base = (uint32_t)__cvta_generic_to_shared(smem);
    const uint32_t xb = base + (p ? XS1 : XS0);
    const uint32_t wb = base + (p ? WS1 : WS0);
    if (tid == 0) mbar_expect_tx(mbar, 32 * 1024 + NCOL * 1024);
    __syncwarp();
    {   // X row tid (1 KB)
        const int grow = a.gather ? __ldg(a.gather + a.m0 + tid) : tid;
        bulkcp(xb + (uint32_t)tid * 1040, X + (size_t)grow * Hn + koff, 1024, mbar);
    }
    if (tid < NCOL) {   // W row tid (1 KB)
        const int c = tid;
        const int wrow = a.interleave ? ((c >> 3) * Hn + a.jbase + (c & 7)) : (a.col0 + c);
        bulkcp(wb + (uint32_t)c * 1040, W + (size_t)wrow * a.ldw + koff, 1024, mbar);
    }
}

// Result: sums[o], o = b*4CQ + cq*4 + j; actual local col c = cq + CQ*j
template<int CQ>   // NCOL = 4*CQ; threads: CQ(c) x 8(b) x (64/CQ)(k-slices)
__device__ void gemm3(const TileArgs& a, char* smem, unsigned* ph2) {
    const int tid = threadIdx.x;
    const int cq = tid % CQ, bq = (tid / CQ) % 8, ks = tid / (CQ * 8);
    const uint32_t base = (uint32_t)__cvta_generic_to_shared(smem);
    const uint32_t mb0 = base + MBARO, mb1 = base + MBARO + 8;
    unsigned long long acc[2][4][4];
    #pragma unroll
    for (int i = 0; i < 4; i++)
        #pragma unroll
        for (int j = 0; j < 4; j++) { acc[0][i][j] = 0ull; acc[1][i][j] = 0ull; }

    stage3<4 * CQ>(a, 0, smem, 0, mb0);
    for (int ch = 0; ch < a.nch; ch++) {
        const int b = ch & 1;
        // buffer 1-b was fully consumed in iter ch-1 (ends with __syncthreads)
        if (ch + 1 < a.nch) stage3<4 * CQ>(a, ch + 1, smem, 1 - b, b ? mb0 : mb1);
        mbar_wait(b ? mb1 : mb0, ph2[b]);
        ph2[b] ^= 1u;
        const float* xb = (const float*)(smem + (b ? XS1 : XS0));
        const float* wb = (const float*)(smem + (b ? WS1 : WS0));
        #pragma unroll
        for (int u = 0; u < CQ; u++) {
            const int k4 = ks * CQ + u;
            unsigned long long xr[4][2], wr[4][2];
            #pragma unroll
            for (int i = 0; i < 4; i++) {
                const ulonglong2 v =
                    *(const ulonglong2*)(xb + (bq + 8 * i) * 260 + k4 * 4);
                xr[i][0] = v.x; xr[i][1] = v.y;
            }
            #pragma unroll
            for (int j = 0; j < 4; j++) {
                const int c = cq + CQ * j;
                const ulonglong2 v = *(const ulonglong2*)(wb + c * 260 + k4 * 4);
                wr[j][0] = v.x; wr[j][1] = v.y;
            }
            #pragma unroll
            for (int i = 0; i < 4; i++)
                #pragma unroll
                for (int j = 0; j < 4; j++) {
                    ffma2(acc[0][i][j], xr[i][0], wr[j][0]);
                    ffma2(acc[1][i][j], xr[i][1], wr[j][1]);
                }
        }
        __syncthreads();   // all threads done with buffer b before it is restaged
    }
    // in-block reduction over 64/CQ k-slices
    const int NOUT = 32 * 4 * CQ, KS = 64 / CQ;
    float* red = (float*)(smem + REDO);
    #pragma unroll
    for (int i = 0; i < 4; i++) {
        const int b = bq + 8 * i;
        float4 v;
        v.x = lo32(acc[0][i][0]) + hi32(acc[0][i][0]) + lo32(acc[1][i][0]) + hi32(acc[1][i][0]);
        v.y = lo32(acc[0][i][1]) + hi32(acc[0][i][1]) + lo32(acc[1][i][1]) + hi32(acc[1][i][1]);
        v.z = lo32(acc[0][i][2]) + hi32(acc[0][i][2]) + lo32(acc[1][i][2]) + hi32(acc[1][i][2]);
        v.w = lo32(acc[0][i][3]) + hi32(acc[0][i][3]) + lo32(acc[1][i][3]) + hi32(acc[1][i][3]);
        *(float4*)(red + ks * NOUT + b * (4 * CQ) + cq * 4) = v;
    }
    __syncthreads();
    float* sums = (float*)(smem + SUMSO);
    for (int o = tid; o < NOUT; o += NT) {
        float s = 0.f;
        for (int k = 0; k < KS; k++) s += red[k * NOUT + o];
        sums[o] = s;
    }
    __syncthreads();
}

// ---------------- epilogues ----------------
__device__ __forceinline__ void lstm_epi(const float* sums, int tile, int t, int layer,
    const float* b_ih, const float* b_hh, float* hNew, float* cSt) {
    const int tid = threadIdx.x;
    if (tid < 256) {
        const int b = tid & 31, jj = tid >> 5;   // jj = cq
        const int col = tile * 8 + jj;
        const float4 g = *(const float4*)(sums + b * 32 + jj * 4);   // j=0..3 gates
        const float* bi = b_ih + layer * Gn;
        const float* bh = b_hh + layer * Gn;
        float gi = g.x + bi[col] + bh[col];
        float gf = g.y + bi[Hn + col] + bh[Hn + col];
        float gg = g.z + bi[2 * Hn + col] + bh[2 * Hn + col];
        float go = g.w + bi[3 * Hn + col] + bh[3 * Hn + col];
        if (layer == 0) {
            const float* pr = g_pre + ((size_t)t * Bn + b) * Gn;
            gi += pr[col]; gf += pr[Hn + col]; gg += pr[2 * Hn + col]; go += pr[3 * Hn + col];
        }
        gi = 1.f / (1.f + expf(-gi));
        gf = 1.f / (1.f + expf(-gf));
        gg = tanhf(gg);
        go = 1.f / (1.f + expf(-go));
        float* c = cSt + layer * Bn * Hn;
        const float cn = gf * c[b * Hn + col] + gi * gg;
        c[b * Hn + col] = cn;
        (hNew + layer * Bn * Hn)[b * Hn + col] = go * tanhf(cn);
    }
    __syncthreads();
}

__device__ void attn(const float* __restrict__ contexts, char* smem) {
    const int b = blockIdx.x, tid = threadIdx.x;
    float* gam = (float*)smem;
    float* sc = gam + Hn;
    for (int j = tid; j < Hn; j += NT) gam[j] = g_gamma[b * Hn + j];
    __syncthreads();
    const int w = tid >> 5, lane = tid & 31;
    for (int s = w; s < Sn; s += 16) {
        const float* cr = contexts + ((size_t)b * Sn + s) * Hn;
        float p = 0.f;
        for (int j = lane; j < Hn; j += 32) p += cr[j] * gam[j];
        #pragma unroll
        for (int o = 16; o; o >>= 1) p += __shfl_down_sync(0xffffffffu, p, o);
        if (!lane) sc[s] = p;
    }
    __syncthreads();
    if (tid == 0) {
        float m = -1e30f;
        for (int i = 0; i < Sn; i++) m = fmaxf(m, sc[i]);
        float su = 0.f;
        for (int i = 0; i < Sn; i++) { float e = expf(sc[i] - m); sc[i] = e; su += e; }
        const float inv = 1.f / su;
        for (int i = 0; i < Sn; i++) sc[i] *= inv;
    }
    __syncthreads();
    for (int j = tid; j < Hn; j += NT) {
        float a2 = 0.f;
        #pragma unroll 8
        for (int s = 0; s < Sn; s++) a2 += sc[s] * contexts[((size_t)b * Sn + s) * Hn + j];
        g_ctx[b * Hn + j] = a2;
    }
    __syncthreads();
}

// ---------------- persistent kernel ----------------
__global__ void __launch_bounds__(NT, 1) decoder(
    const int* __restrict__ tokens, const float* __restrict__ contexts,
    const float* __restrict__ emb,
    const float* __restrict__ W_ih, const float* __restrict__ W_hh,
    const float* __restrict__ b_ih, const float* __restrict__ b_hh,
    const float* __restrict__ W_in, const float* __restrict__ b_in,
    const float* __restrict__ W_out, const float* __restrict__ b_out,
    const float* __restrict__ h0, const float* __restrict__ c0,
    float* __restrict__ out)
{
    extern __shared__ char smem[];
    const unsigned base = g_rel;
    unsigned ph = 0;
    unsigned ph2[2] = {0u, 0u};      // mbarrier parity per buffer
    const int tid = threadIdx.x;
    float* sums = (float*)(smem + SUMSO);

    // mbarrier init (fresh every launch/replay)
    {
        const uint32_t sb = (uint32_t)__cvta_generic_to_shared(smem);
        if (tid == 0) {
            mbar_init(sb + MBARO, 1);
            mbar_init(sb + MBARO + 8, 1);
        }
        asm volatile("fence.proxy.async.shared::cta;" ::: "memory");
        __syncthreads();
    }

    // state init
    for (int i = blockIdx.x * NT + tid; i < 2 * Bn * Hn; i += NB * NT) {
        g_h[0][i] = h0[i];
        g_c[i] = c0[i];
    }

    // pre-phase: g_pre[t*B+b][gatecol] = emb[tokens] @ W_ih0^T
    for (int tt = blockIdx.x; tt < 64 * 128; tt += NB) {
        const int ctile = tt & 127;
        TileArgs a;
        a.X1 = emb; a.X2 = emb; a.W1 = W_ih; a.W2 = W_ih; a.ldw = Hn;
        a.interleave = 1; a.jbase = ctile * 8; a.col0 = 0;
        a.gather = tokens; a.m0 = (tt >> 7) * 32; a.nch = 4;
        gemm3<8>(a, smem, ph2);
        #pragma unroll
        for (int r = 0; r < 2; r++) {
            const int o = tid + r * 512;
            const int b = o >> 5, cl = o & 31;
            const int col = (cl & 3) * Hn + ctile * 8 + (cl >> 2);
            g_pre[(size_t)(a.m0 + b) * Gn + col] = sums[o];
        }
        __syncthreads();
    }
    gsync(base + ++ph);

    for (int t = 0; t < Tn; t++) {
        const int p = t & 1;
        float* hOld = g_h[p];
        float* hNew = g_h[p ^ 1];

        // A: layer-0 gates = pre[t] + h0_old @ W_hh0^T
        {
            TileArgs a;
            a.X1 = hOld; a.X2 = hOld; a.W1 = W_hh; a.W2 = W_hh; a.ldw = Hn;
            a.interleave = 1; a.jbase = blockIdx.x * 8; a.col0 = 0;
            a.gather = nullptr; a.m0 = 0; a.nch = 4;
            gemm3<8>(a, smem, ph2);
            lstm_epi(sums, blockIdx.x, t, 0, b_ih, b_hh, hNew, g_c);
        }
        gsync(base + ++ph);

        // B: layer-1 gates = h0_new @ W_ih1^T + h1_old @ W_hh1^T (K=2048)
        {
            TileArgs a;
            a.X1 = hNew; a.X2 = hOld + Bn * Hn;
            a.W1 = W_ih + (size_t)Gn * Hn; a.W2 = W_hh + (size_t)Gn * Hn; a.ldw = Hn;
            a.interleave = 1; a.jbase = blockIdx.x * 8; a.col0 = 0;
            a.gather = nullptr; a.m0 = 0; a.nch = 8;
            gemm3<8>(a, smem, ph2);
            lstm_epi(sums, blockIdx.x, t, 1, b_ih, b_hh, hNew, g_c);
        }
        gsync(base + ++ph);

        // C: gamma = h1 @ W_in^T + b_in  (128 blocks x 8 cols)
        {
            TileArgs a;
            a.X1 = hNew + Bn * Hn; a.X2 = a.X1;
            a.W1 = W_in; a.W2 = W_in; a.ldw = Hn;
            a.interleave = 0; a.jbase = 0; a.col0 = blockIdx.x * 8;
            a.gather = nullptr; a.m0 = 0; a.nch = 4;
            gemm3<2>(a, smem, ph2);
            if (tid < 256) {
                const int b = tid >> 3, cl = tid & 7;
                const int col = a.col0 + (cl >> 2) + 2 * (cl & 3);
                g_gamma[b * Hn + col] = sums[tid] + b_in[col];
            }
            __syncthreads();
        }
        gsync(base + ++ph);

        // D: attention (blocks 0..31) || opart = h1 @ W_out[:,H:]^T (blocks 32..95)
        if (blockIdx.x < 32) {
            attn(contexts, smem);
        } else if (blockIdx.x < 96) {
            TileArgs a;
            a.X1 = hNew + Bn * Hn; a.X2 = a.X1;
            a.W1 = W_out + Hn; a.W2 = a.W1; a.ldw = 2 * Hn;
            a.interleave = 0; a.jbase = 0; a.col0 = (blockIdx.x - 32) * 16;
            a.gather = nullptr; a.m0 = 0; a.nch = 4;
            gemm3<4>(a, smem, ph2);
            const int b = tid >> 4, cl = tid & 15;
            const int col = a.col0 + (cl >> 2) + 4 * (cl & 3);
            g_opart[b * Hn + col] = sums[tid];
            __syncthreads();
        }
        gsync(base + ++ph);

        // E: out[t] = tanh(ctx @ W_out[:, :H]^T + opart + b_out)
        {
            TileArgs a;
            a.X1 = g_ctx; a.X2 = g_ctx; a.W1 = W_out; a.W2 = W_out; a.ldw = 2 * Hn;
            a.interleave = 0; a.jbase = 0; a.col0 = blockIdx.x * 8;
            a.gather = nullptr; a.m0 = 0; a.nch = 4;
            gemm3<2>(a, smem, ph2);
            if (tid < 256) {
                const int b = tid >> 3, cl = tid & 7;
                const int col = a.col0 + (cl >> 2) + 2 * (cl & 3);
                out[(size_t)t * Bn * Hn + b * Hn + col] =
                    tanhf(sums[tid] + g_opart[b * Hn + col] + b_out[col]);
            }
            __syncthreads();
        }
        // next A's gsync covers E
    }
    gsync(base + ++ph);

    // emit hT (in g_h[0] after even Tn) and cT
    for (int i = blockIdx.x * NT + tid; i < 2 * Bn * Hn; i += NB * NT) {
        out[(size_t)Tn * Bn * Hn + i] = g_h[0][i];
        out[(size_t)Tn * Bn * Hn + 2 * Bn * Hn + i] = g_c[i];
    }
}

// ---------------- launch ----------------
extern "C" void kernel_launch(void* const* d_in, const int* in_sizes, int n_in,
                              void* d_out, int out_size)
{
    const int*   tokens   = (const int*)  d_in[0];
    const float* h0       = (const float*)d_in[1];
    const float* c0       = (const float*)d_in[2];
    const float* contexts = (const float*)d_in[3];
    const float* emb      = (const float*)d_in[4];
    const float* W_ih     = (const float*)d_in[5];
    const float* W_hh     = (const float*)d_in[6];
    const float* b_ih     = (const float*)d_in[7];
    const float* b_hh     = (const float*)d_in[8];
    const float* W_in     = (const float*)d_in[9];
    const float* b_in     = (const float*)d_in[10];
    const float* W_out    = (const float*)d_in[11];
    const float* b_out    = (const float*)d_in[12];
    float* out = (float*)d_out;

    static bool configured = false;
    if (!configured) {
        cudaFuncSetAttribute(decoder, cudaFuncAttributeMaxDynamicSharedMemorySize, SMEM_BYTES);
        configured = true;
    }
    decoder<<<NB, NT, SMEM_BYTES>>>(tokens, contexts, emb, W_ih, W_hh, b_ih, b_hh,
                                    W_in, b_in, W_out, b_out, h0, c0, out);
}